// round 1
// baseline (speedup 1.0000x reference)
#include <cuda_runtime.h>
#include <cuda_bf16.h>

// out[i] = sum_j (mu[i,j] + softplus(rho[i,j]) * eps_w[i,j]) * x[j]
//          + bias_mu[i] + softplus(bias_rho[i]) * eps_b[i]
//
// Shapes: x(4096), mu/rho/eps_w(8192,4096), bias_*(8192), out(8192) fp32.
// HBM-bound: 384 MB mandatory reads. Strategy: float4 streaming, x in smem,
// one warp per output row, warp-shuffle reduction.

#define IN_SIZE   4096
#define OUT_SIZE  8192
#define VEC4      (IN_SIZE / 4)      // 1024 float4 per row
#define THREADS   256
#define WARPS     (THREADS / 32)     // 8 rows per block
#define GRID      (OUT_SIZE / WARPS) // 1024 blocks

__device__ __forceinline__ float softplus_f(float v) {
    // numerically stable: max(v,0) + log1p(exp(-|v|))
    return fmaxf(v, 0.0f) + log1pf(__expf(-fabsf(v)));
}

__global__ __launch_bounds__(THREADS, 8)
void variational_linear_kernel(
    const float* __restrict__ x,
    const float* __restrict__ mu,
    const float* __restrict__ rho,
    const float* __restrict__ bias_mu,
    const float* __restrict__ bias_rho,
    const float* __restrict__ eps_w,
    const float* __restrict__ eps_b,
    float* __restrict__ out)
{
    __shared__ float4 xs[VEC4];  // 16 KB

    const int tid = threadIdx.x;

    // Cooperative load of x into shared memory (float4).
    const float4* x4 = reinterpret_cast<const float4*>(x);
    #pragma unroll
    for (int i = tid; i < VEC4; i += THREADS) {
        xs[i] = x4[i];
    }
    __syncthreads();

    const int warp = tid >> 5;
    const int lane = tid & 31;
    const int row  = blockIdx.x * WARPS + warp;

    const size_t row_off = (size_t)row * IN_SIZE;
    const float4* mu4  = reinterpret_cast<const float4*>(mu    + row_off);
    const float4* rho4 = reinterpret_cast<const float4*>(rho   + row_off);
    const float4* ew4  = reinterpret_cast<const float4*>(eps_w + row_off);

    float acc = 0.0f;

    // 1024 float4 per row / 32 lanes = 32 iterations. Unroll 4 for MLP:
    // 12 outstanding LDG.128 per warp per unrolled group.
    #pragma unroll 4
    for (int i = lane; i < VEC4; i += 32) {
        float4 m  = mu4[i];
        float4 r  = rho4[i];
        float4 e  = ew4[i];
        float4 xv = xs[i];

        float w0 = fmaf(softplus_f(r.x), e.x, m.x);
        float w1 = fmaf(softplus_f(r.y), e.y, m.y);
        float w2 = fmaf(softplus_f(r.z), e.z, m.z);
        float w3 = fmaf(softplus_f(r.w), e.w, m.w);

        acc = fmaf(w0, xv.x, acc);
        acc = fmaf(w1, xv.y, acc);
        acc = fmaf(w2, xv.z, acc);
        acc = fmaf(w3, xv.w, acc);
    }

    // Warp reduction.
    #pragma unroll
    for (int off = 16; off > 0; off >>= 1) {
        acc += __shfl_xor_sync(0xFFFFFFFFu, acc, off);
    }

    if (lane == 0) {
        float b = fmaf(softplus_f(bias_rho[row]), eps_b[row], bias_mu[row]);
        out[row] = acc + b;
    }
}

extern "C" void kernel_launch(void* const* d_in, const int* in_sizes, int n_in,
                              void* d_out, int out_size)
{
    const float* x        = (const float*)d_in[0];
    const float* mu       = (const float*)d_in[1];
    const float* rho      = (const float*)d_in[2];
    const float* bias_mu  = (const float*)d_in[3];
    const float* bias_rho = (const float*)d_in[4];
    const float* eps_w    = (const float*)d_in[5];
    const float* eps_b    = (const float*)d_in[6];
    float* out = (float*)d_out;

    variational_linear_kernel<<<GRID, THREADS>>>(
        x, mu, rho, bias_mu, bias_rho, eps_w, eps_b, out);
}